// round 3
// baseline (speedup 1.0000x reference)
#include <cuda_runtime.h>
#include <math.h>

#define PNT 20
#define KNN 8
#define PS  22          // padded point stride (even for float2, limits bank conflicts)
#define D0  128
#define NTHREADS 256

__device__ __forceinline__ unsigned long long pack2f(float x, float y){
    return ((unsigned long long)__float_as_uint(y) << 32) | (unsigned long long)__float_as_uint(x);
}
__device__ __forceinline__ unsigned long long ffma2(unsigned long long a, unsigned long long b, unsigned long long c){
    unsigned long long d;
    asm("fma.rn.f32x2 %0, %1, %2, %3;" : "=l"(d) : "l"(a), "l"(b), "l"(c));
    return d;
}
__device__ __forceinline__ float warp_sum(float v){
    #pragma unroll
    for(int m=16;m>0;m>>=1) v += __shfl_xor_sync(0xffffffffu, v, m);
    return v;
}

struct SmemT {
    float As[512*PS];     // activations, feature-major: As[f*PS + p]
    float Bw[512*PS];     // xw scratch, feature-major
    float d2[PNT*PNT];
    float sq[PNT];
    float dinv[PNT];
    float Nm[PNT*PNT];    // dense normalized adjacency: out = Nm @ xw
    int   knn[PNT*KNN];
    int   deg[PNT];
    float msm[128];
    float hsm[64];
    float lsm[4];
};

// ---- kNN graph + normalization matrix from current As (IN features) ----
template<int IN>
__device__ void build_graph(SmemT& S, int tid){
    const int warp = tid >> 5, lane = tid & 31;
    // sq[i] = ||x_i||^2
    for(int i=warp;i<PNT;i+=8){
        float s=0.f;
        #pragma unroll 4
        for(int f=lane;f<IN;f+=32){ float v=S.As[f*PS+i]; s=fmaf(v,v,s); }
        s = warp_sum(s);
        if(lane==0) S.sq[i]=s;
    }
    __syncthreads();
    // d2[i][j] = sq_i + sq_j - 2*dot  (exact reference formula), symmetric pairs
    for(int q=warp;q<190;q+=8){
        int i=0, rem=q;
        while(rem >= PNT-1-i){ rem -= PNT-1-i; i++; }
        int j=i+1+rem;
        float s=0.f;
        #pragma unroll 4
        for(int f=lane;f<IN;f+=32) s = fmaf(S.As[f*PS+i], S.As[f*PS+j], s);
        s = warp_sum(s);
        if(lane==0){
            float v = S.sq[i]+S.sq[j]-2.f*s;
            S.d2[i*PNT+j]=v; S.d2[j*PNT+i]=v;
        }
    }
    // self-distance is always the row minimum in the reference (≈0 vs O(IN));
    // force -inf so "drop argsort position 0" == "drop self"
    if(tid<PNT) S.d2[tid*PNT+tid] = __int_as_float(0xff800000);
    __syncthreads();
    // stable K-smallest selection (matches stable argsort tie-breaking)
    if(tid<PNT){
        float row[PNT];
        #pragma unroll
        for(int j=0;j<PNT;j++) row[j]=S.d2[tid*PNT+j];
        unsigned used=0;
        #pragma unroll
        for(int k=0;k<KNN+1;k++){
            float best = __int_as_float(0x7f800000); int bj=0;
            #pragma unroll
            for(int j=0;j<PNT;j++){
                if( !((used>>j)&1u) && row[j] < best ){ best=row[j]; bj=j; }
            }
            used |= 1u<<bj;
            if(k>0) S.knn[tid*KNN + (k-1)] = bj;   // first pick = self, dropped
        }
        S.deg[tid]=1;   // self loop
    }
    for(int q=tid;q<PNT*PNT;q+=NTHREADS) S.Nm[q]=0.f;
    __syncthreads();
    if(tid<PNT*KNN) atomicAdd(&S.deg[S.knn[tid]], 1);   // in-degree at targets
    __syncthreads();
    if(tid<PNT) S.dinv[tid] = 1.f/sqrtf((float)S.deg[tid]);
    __syncthreads();
    if(tid<PNT*KNN){
        int u = tid>>3;                 // source
        int t = S.knn[tid];             // target
        S.Nm[t*PNT+u] = S.dinv[t]*S.dinv[u];
    }
    if(tid<PNT) S.Nm[tid*PNT+tid] = S.dinv[tid]*S.dinv[tid];
    __syncthreads();
}

// ---- xw = As^T(W) : Bw[o][p] = sum_i As[i][p]*W[i][o], packed f32x2 FMAs ----
template<int IN,int OUT,int COLS,int GROUPS>
__device__ void gemm(SmemT& S, const float* __restrict__ W, int tid){
    constexpr int CU   = OUT/COLS;      // column units across threads
    constexpr int ROWS = PNT/GROUPS;
    constexpr int RH   = ROWS/2;
    const int o  = (tid % CU)*COLS;
    const int p0 = (tid / CU)*ROWS;
    unsigned long long acc[COLS][RH];
    #pragma unroll
    for(int c=0;c<COLS;c++){
        #pragma unroll
        for(int r=0;r<RH;r++) acc[c][r]=0ull;
    }
    #pragma unroll 2
    for(int i=0;i<IN;i++){
        const unsigned long long* a = reinterpret_cast<const unsigned long long*>(&S.As[i*PS+p0]);
        unsigned long long wp0, wp1=0;
        if constexpr (COLS==2){
            float2 w = *reinterpret_cast<const float2*>(W + i*OUT + o);
            wp0 = pack2f(w.x,w.x); wp1 = pack2f(w.y,w.y);
        } else {
            float w = W[i*OUT+o]; wp0 = pack2f(w,w);
        }
        #pragma unroll
        for(int r=0;r<RH;r++){
            unsigned long long av = a[r];
            acc[0][r] = ffma2(av, wp0, acc[0][r]);
            if constexpr (COLS==2) acc[1][r] = ffma2(av, wp1, acc[1][r]);
        }
    }
    #pragma unroll
    for(int c=0;c<COLS;c++){
        unsigned long long* dst = reinterpret_cast<unsigned long long*>(&S.Bw[(o+c)*PS+p0]);
        #pragma unroll
        for(int r=0;r<RH;r++) dst[r]=acc[c][r];
    }
}

// ---- As[o][t] = relu( (Nm @ xw)[t][o] + bias[o] ) ----
template<int OUT>
__device__ void aggregate(SmemT& S, const float* __restrict__ bias, int tid){
    for(int o=tid;o<OUT;o+=NTHREADS){
        float bo = bias[o];
        float acc[PNT];
        #pragma unroll
        for(int t=0;t<PNT;t++) acc[t]=0.f;
        for(int s=0;s<PNT;s++){
            float v = S.Bw[o*PS+s];
            #pragma unroll
            for(int t=0;t<PNT;t++) acc[t] = fmaf(S.Nm[t*PNT+s], v, acc[t]);
        }
        #pragma unroll
        for(int t=0;t<PNT;t++) S.As[o*PS+t] = fmaxf(acc[t]+bo, 0.f);
    }
}

__global__ void __launch_bounds__(NTHREADS,2)
gnn_kernel(const float* __restrict__ x,
           const float* __restrict__ W1, const float* __restrict__ b1,
           const float* __restrict__ W2, const float* __restrict__ b2,
           const float* __restrict__ W3, const float* __restrict__ b3,
           const float* __restrict__ W4, const float* __restrict__ b4,
           const float* __restrict__ W5, const float* __restrict__ b5,
           float* __restrict__ out)
{
    extern __shared__ char smem_raw[];
    SmemT& S = *reinterpret_cast<SmemT*>(smem_raw);
    const int tid = threadIdx.x;
    const long long b = blockIdx.x;

    // load sample b, transpose to feature-major
    const float* xb = x + b*(long long)(PNT*D0);
    for(int q=tid;q<PNT*D0;q+=NTHREADS){
        int p=q>>7, d=q&127;
        S.As[d*PS+p]=xb[q];
    }
    __syncthreads();

    // layer 1: 128 -> 256
    build_graph<128>(S,tid);
    gemm<128,256,2,2>(S,W1,tid);
    __syncthreads();
    aggregate<256>(S,b1,tid);
    __syncthreads();
    // layer 2: 256 -> 512
    build_graph<256>(S,tid);
    gemm<256,512,2,1>(S,W2,tid);
    __syncthreads();
    aggregate<512>(S,b2,tid);
    __syncthreads();
    // layer 3: 512 -> 128
    build_graph<512>(S,tid);
    gemm<512,128,1,2>(S,W3,tid);
    __syncthreads();
    aggregate<128>(S,b3,tid);
    __syncthreads();

    // head: mean pool -> fc 128x64 relu -> fc 64x3 -> softmax
    if(tid<128){
        float s=0.f;
        #pragma unroll
        for(int p=0;p<PNT;p++) s+=S.As[tid*PS+p];
        S.msm[tid]=s*(1.f/PNT);
    }
    __syncthreads();
    if(tid<64){
        float a=b4[tid];
        #pragma unroll 4
        for(int f=0;f<128;f++) a=fmaf(S.msm[f], W4[f*64+tid], a);
        S.hsm[tid]=fmaxf(a,0.f);
    }
    __syncthreads();
    if(tid<3){
        float a=b5[tid];
        #pragma unroll
        for(int j=0;j<64;j++) a=fmaf(S.hsm[j], W5[j*3+tid], a);
        S.lsm[tid]=a;
    }
    __syncthreads();
    if(tid==0){
        float l0=S.lsm[0], l1=S.lsm[1], l2=S.lsm[2];
        float m=fmaxf(l0,fmaxf(l1,l2));
        float e0=expf(l0-m), e1=expf(l1-m), e2=expf(l2-m);
        float s=e0+e1+e2;
        out[b*3+0]=e0/s; out[b*3+1]=e1/s; out[b*3+2]=e2/s;
    }
}

extern "C" void kernel_launch(void* const* d_in, const int* in_sizes, int n_in,
                              void* d_out, int out_size){
    const float* x  = (const float*)d_in[0];
    const float* W1 = (const float*)d_in[1];
    const float* b1 = (const float*)d_in[2];
    const float* W2 = (const float*)d_in[3];
    const float* b2 = (const float*)d_in[4];
    const float* W3 = (const float*)d_in[5];
    const float* b3 = (const float*)d_in[6];
    const float* W4 = (const float*)d_in[7];
    const float* b4 = (const float*)d_in[8];
    const float* W5 = (const float*)d_in[9];
    const float* b5 = (const float*)d_in[10];
    float* out = (float*)d_out;

    int N = in_sizes[0]/(PNT*D0);
    size_t smem = sizeof(SmemT);
    cudaFuncSetAttribute(gnn_kernel, cudaFuncAttributeMaxDynamicSharedMemorySize, (int)smem);
    gnn_kernel<<<N, NTHREADS, smem>>>(x, W1,b1, W2,b2, W3,b3, W4,b4, W5,b5, out);
}

// round 4
// speedup vs baseline: 1.0007x; 1.0007x over previous
#include <cuda_runtime.h>
#include <math.h>

#define PNT 20
#define KNN 8
#define PS  22          // padded point stride (even for float2, limits bank conflicts)
#define D0  128
#define NTHREADS 256

__device__ __forceinline__ unsigned long long pack2f(float x, float y){
    return ((unsigned long long)__float_as_uint(y) << 32) | (unsigned long long)__float_as_uint(x);
}
__device__ __forceinline__ unsigned long long ffma2(unsigned long long a, unsigned long long b, unsigned long long c){
    unsigned long long d;
    asm("fma.rn.f32x2 %0, %1, %2, %3;" : "=l"(d) : "l"(a), "l"(b), "l"(c));
    return d;
}
__device__ __forceinline__ float warp_sum(float v){
    #pragma unroll
    for(int m=16;m>0;m>>=1) v += __shfl_xor_sync(0xffffffffu, v, m);
    return v;
}

struct SmemT {
    float As[512*PS];     // activations, feature-major: As[f*PS + p]
    float Bw[512*PS];     // xw scratch, feature-major
    float d2[PNT*PNT];
    float sq[PNT];
    float dinv[PNT];
    float Nm[PNT*PNT];    // dense normalized adjacency: out = Nm @ xw
    int   knn[PNT*KNN];
    int   deg[PNT];
    float msm[128];
    float hsm[64];
    float lsm[4];
};

// ---- kNN graph + normalization matrix from current As (IN features) ----
template<int IN>
__device__ void build_graph(SmemT& S, int tid){
    const int warp = tid >> 5, lane = tid & 31;
    // sq[i] = ||x_i||^2
    for(int i=warp;i<PNT;i+=8){
        float s=0.f;
        #pragma unroll 4
        for(int f=lane;f<IN;f+=32){ float v=S.As[f*PS+i]; s=fmaf(v,v,s); }
        s = warp_sum(s);
        if(lane==0) S.sq[i]=s;
    }
    __syncthreads();
    // d2[i][j] = sq_i + sq_j - 2*dot  (exact reference formula), symmetric pairs
    for(int q=warp;q<190;q+=8){
        int i=0, rem=q;
        while(rem >= PNT-1-i){ rem -= PNT-1-i; i++; }
        int j=i+1+rem;
        float s=0.f;
        #pragma unroll 4
        for(int f=lane;f<IN;f+=32) s = fmaf(S.As[f*PS+i], S.As[f*PS+j], s);
        s = warp_sum(s);
        if(lane==0){
            float v = S.sq[i]+S.sq[j]-2.f*s;
            S.d2[i*PNT+j]=v; S.d2[j*PNT+i]=v;
        }
    }
    // self-distance is always the row minimum in the reference (≈0 vs O(IN));
    // force -inf so "drop argsort position 0" == "drop self"
    if(tid<PNT) S.d2[tid*PNT+tid] = __int_as_float(0xff800000);
    __syncthreads();
    // stable K-smallest selection (matches stable argsort tie-breaking)
    if(tid<PNT){
        float row[PNT];
        #pragma unroll
        for(int j=0;j<PNT;j++) row[j]=S.d2[tid*PNT+j];
        unsigned used=0;
        #pragma unroll
        for(int k=0;k<KNN+1;k++){
            float best = __int_as_float(0x7f800000); int bj=0;
            #pragma unroll
            for(int j=0;j<PNT;j++){
                if( !((used>>j)&1u) && row[j] < best ){ best=row[j]; bj=j; }
            }
            used |= 1u<<bj;
            if(k>0) S.knn[tid*KNN + (k-1)] = bj;   // first pick = self, dropped
        }
        S.deg[tid]=1;   // self loop
    }
    for(int q=tid;q<PNT*PNT;q+=NTHREADS) S.Nm[q]=0.f;
    __syncthreads();
    if(tid<PNT*KNN) atomicAdd(&S.deg[S.knn[tid]], 1);   // in-degree at targets
    __syncthreads();
    if(tid<PNT) S.dinv[tid] = 1.f/sqrtf((float)S.deg[tid]);
    __syncthreads();
    if(tid<PNT*KNN){
        int u = tid>>3;                 // source
        int t = S.knn[tid];             // target
        S.Nm[t*PNT+u] = S.dinv[t]*S.dinv[u];
    }
    if(tid<PNT) S.Nm[tid*PNT+tid] = S.dinv[tid]*S.dinv[tid];
    __syncthreads();
}

// ---- xw = As^T(W) : Bw[o][p] = sum_i As[i][p]*W[i][o], packed f32x2 FMAs ----
template<int IN,int OUT,int COLS,int GROUPS>
__device__ void gemm(SmemT& S, const float* __restrict__ W, int tid){
    constexpr int CU   = OUT/COLS;      // column units across threads
    constexpr int ROWS = PNT/GROUPS;
    constexpr int RH   = ROWS/2;
    const int o  = (tid % CU)*COLS;
    const int p0 = (tid / CU)*ROWS;
    unsigned long long acc[COLS][RH];
    #pragma unroll
    for(int c=0;c<COLS;c++){
        #pragma unroll
        for(int r=0;r<RH;r++) acc[c][r]=0ull;
    }
    #pragma unroll 2
    for(int i=0;i<IN;i++){
        const unsigned long long* a = reinterpret_cast<const unsigned long long*>(&S.As[i*PS+p0]);
        unsigned long long wp0, wp1=0;
        if constexpr (COLS==2){
            float2 w = *reinterpret_cast<const float2*>(W + i*OUT + o);
            wp0 = pack2f(w.x,w.x); wp1 = pack2f(w.y,w.y);
        } else {
            float w = W[i*OUT+o]; wp0 = pack2f(w,w);
        }
        #pragma unroll
        for(int r=0;r<RH;r++){
            unsigned long long av = a[r];
            acc[0][r] = ffma2(av, wp0, acc[0][r]);
            if constexpr (COLS==2) acc[1][r] = ffma2(av, wp1, acc[1][r]);
        }
    }
    #pragma unroll
    for(int c=0;c<COLS;c++){
        unsigned long long* dst = reinterpret_cast<unsigned long long*>(&S.Bw[(o+c)*PS+p0]);
        #pragma unroll
        for(int r=0;r<RH;r++) dst[r]=acc[c][r];
    }
}

// ---- As[o][t] = relu( (Nm @ xw)[t][o] + bias[o] ) ----
template<int OUT>
__device__ void aggregate(SmemT& S, const float* __restrict__ bias, int tid){
    for(int o=tid;o<OUT;o+=NTHREADS){
        float bo = bias[o];
        float acc[PNT];
        #pragma unroll
        for(int t=0;t<PNT;t++) acc[t]=0.f;
        for(int s=0;s<PNT;s++){
            float v = S.Bw[o*PS+s];
            #pragma unroll
            for(int t=0;t<PNT;t++) acc[t] = fmaf(S.Nm[t*PNT+s], v, acc[t]);
        }
        #pragma unroll
        for(int t=0;t<PNT;t++) S.As[o*PS+t] = fmaxf(acc[t]+bo, 0.f);
    }
}

__global__ void __launch_bounds__(NTHREADS,2)
gnn_kernel(const float* __restrict__ x,
           const float* __restrict__ W1, const float* __restrict__ b1,
           const float* __restrict__ W2, const float* __restrict__ b2,
           const float* __restrict__ W3, const float* __restrict__ b3,
           const float* __restrict__ W4, const float* __restrict__ b4,
           const float* __restrict__ W5, const float* __restrict__ b5,
           float* __restrict__ out)
{
    extern __shared__ char smem_raw[];
    SmemT& S = *reinterpret_cast<SmemT*>(smem_raw);
    const int tid = threadIdx.x;
    const long long b = blockIdx.x;

    // load sample b, transpose to feature-major
    const float* xb = x + b*(long long)(PNT*D0);
    for(int q=tid;q<PNT*D0;q+=NTHREADS){
        int p=q>>7, d=q&127;
        S.As[d*PS+p]=xb[q];
    }
    __syncthreads();

    // layer 1: 128 -> 256
    build_graph<128>(S,tid);
    gemm<128,256,2,2>(S,W1,tid);
    __syncthreads();
    aggregate<256>(S,b1,tid);
    __syncthreads();
    // layer 2: 256 -> 512
    build_graph<256>(S,tid);
    gemm<256,512,2,1>(S,W2,tid);
    __syncthreads();
    aggregate<512>(S,b2,tid);
    __syncthreads();
    // layer 3: 512 -> 128
    build_graph<512>(S,tid);
    gemm<512,128,1,2>(S,W3,tid);
    __syncthreads();
    aggregate<128>(S,b3,tid);
    __syncthreads();

    // head: mean pool -> fc 128x64 relu -> fc 64x3 -> softmax
    if(tid<128){
        float s=0.f;
        #pragma unroll
        for(int p=0;p<PNT;p++) s+=S.As[tid*PS+p];
        S.msm[tid]=s*(1.f/PNT);
    }
    __syncthreads();
    if(tid<64){
        float a=b4[tid];
        #pragma unroll 4
        for(int f=0;f<128;f++) a=fmaf(S.msm[f], W4[f*64+tid], a);
        S.hsm[tid]=fmaxf(a,0.f);
    }
    __syncthreads();
    if(tid<3){
        float a=b5[tid];
        #pragma unroll
        for(int j=0;j<64;j++) a=fmaf(S.hsm[j], W5[j*3+tid], a);
        S.lsm[tid]=a;
    }
    __syncthreads();
    if(tid==0){
        float l0=S.lsm[0], l1=S.lsm[1], l2=S.lsm[2];
        float m=fmaxf(l0,fmaxf(l1,l2));
        float e0=expf(l0-m), e1=expf(l1-m), e2=expf(l2-m);
        float s=e0+e1+e2;
        out[b*3+0]=e0/s; out[b*3+1]=e1/s; out[b*3+2]=e2/s;
    }
}

extern "C" void kernel_launch(void* const* d_in, const int* in_sizes, int n_in,
                              void* d_out, int out_size){
    const float* x  = (const float*)d_in[0];
    const float* W1 = (const float*)d_in[1];
    const float* b1 = (const float*)d_in[2];
    const float* W2 = (const float*)d_in[3];
    const float* b2 = (const float*)d_in[4];
    const float* W3 = (const float*)d_in[5];
    const float* b3 = (const float*)d_in[6];
    const float* W4 = (const float*)d_in[7];
    const float* b4 = (const float*)d_in[8];
    const float* W5 = (const float*)d_in[9];
    const float* b5 = (const float*)d_in[10];
    float* out = (float*)d_out;

    int N = in_sizes[0]/(PNT*D0);
    size_t smem = sizeof(SmemT);
    cudaFuncSetAttribute(gnn_kernel, cudaFuncAttributeMaxDynamicSharedMemorySize, (int)smem);
    gnn_kernel<<<N, NTHREADS, smem>>>(x, W1,b1, W2,b2, W3,b3, W4,b4, W5,b5, out);
}

// round 5
// speedup vs baseline: 1.4019x; 1.4009x over previous
#include <cuda_runtime.h>
#include <math.h>

#define PNT 20
#define KNN 8
#define PS  22          // padded point stride (even for float2)
#define D0  128
#define NTHREADS 256

__device__ __forceinline__ unsigned long long pack2f(float x, float y){
    return ((unsigned long long)__float_as_uint(y) << 32) | (unsigned long long)__float_as_uint(x);
}
__device__ __forceinline__ unsigned long long ffma2(unsigned long long a, unsigned long long b, unsigned long long c){
    unsigned long long d;
    asm("fma.rn.f32x2 %0, %1, %2, %3;" : "=l"(d) : "l"(a), "l"(b), "l"(c));
    return d;
}
__device__ __forceinline__ float warp_sum(float v){
    #pragma unroll
    for(int m=16;m>0;m>>=1) v += __shfl_xor_sync(0xffffffffu, v, m);
    return v;
}

struct SmemT {
    float As[512*PS];     // activations, feature-major: As[f*PS + p]
    float Bw[512*PS];     // xw scratch (k-split partials in row bands)
    float d2[PNT*PNT];
    float sq[PNT];
    float dinv[PNT];
    float NmT[PNT*PS];    // transposed norm adjacency: NmT[s*PS + t]
    int   knn[PNT*KNN];
    int   deg[PNT];
    float msm[128];
    float hsm[64];
    float lsm[4];
};

// ---- kNN graph + normalization matrix from current As (IN features) ----
template<int IN>
__device__ void build_graph(SmemT& S, int tid){
    const int warp = tid >> 5, lane = tid & 31;
    // sq[i] = ||x_i||^2
    for(int i=warp;i<PNT;i+=8){
        float s=0.f;
        #pragma unroll 8
        for(int f=lane;f<IN;f+=32){ float v=S.As[f*PS+i]; s=fmaf(v,v,s); }
        s = warp_sum(s);
        if(lane==0) S.sq[i]=s;
    }
    __syncthreads();
    // d2[i][j] = sq_i + sq_j - 2*dot  (exact reference formula), symmetric pairs
    for(int q=warp;q<190;q+=8){
        int i=0, rem=q;
        while(rem >= PNT-1-i){ rem -= PNT-1-i; i++; }
        int j=i+1+rem;
        float s=0.f;
        #pragma unroll 8
        for(int f=lane;f<IN;f+=32) s = fmaf(S.As[f*PS+i], S.As[f*PS+j], s);
        s = warp_sum(s);
        if(lane==0){
            float v = S.sq[i]+S.sq[j]-2.f*s;
            S.d2[i*PNT+j]=v; S.d2[j*PNT+i]=v;
        }
    }
    // self-distance is always the row minimum in the reference; force -inf
    if(tid<PNT) S.d2[tid*PNT+tid] = __int_as_float(0xff800000);
    __syncthreads();
    // stable K-smallest selection (matches stable argsort tie-breaking)
    if(tid<PNT){
        float row[PNT];
        #pragma unroll
        for(int j=0;j<PNT;j++) row[j]=S.d2[tid*PNT+j];
        unsigned used=0;
        #pragma unroll
        for(int k=0;k<KNN+1;k++){
            float best = __int_as_float(0x7f800000); int bj=0;
            #pragma unroll
            for(int j=0;j<PNT;j++){
                if( !((used>>j)&1u) && row[j] < best ){ best=row[j]; bj=j; }
            }
            used |= 1u<<bj;
            if(k>0) S.knn[tid*KNN + (k-1)] = bj;   // first pick = self, dropped
        }
        S.deg[tid]=1;   // self loop
    }
    for(int q=tid;q<PNT*PS;q+=NTHREADS) S.NmT[q]=0.f;
    __syncthreads();
    if(tid<PNT*KNN) atomicAdd(&S.deg[S.knn[tid]], 1);   // in-degree at targets
    __syncthreads();
    if(tid<PNT) S.dinv[tid] = 1.f/sqrtf((float)S.deg[tid]);
    __syncthreads();
    if(tid<PNT*KNN){
        int u = tid>>3;                 // source
        int t = S.knn[tid];             // target
        S.NmT[u*PS+t] = S.dinv[t]*S.dinv[u];
    }
    if(tid<PNT) S.NmT[tid*PS+tid] = S.dinv[tid]*S.dinv[tid];
    __syncthreads();
}

// ---- Bw[o + kg*OUT][p] = sum_{i in kg's K-slice} As[i][p]*W[i][o] ----
// COLS=2 everywhere; KSPLIT chosen so OUT/2*KSPLIT == NTHREADS (W read 1x per CTA).
// Register-pipelined weight prefetch (PF=8) hides L2 latency.
template<int IN,int OUT,int KSPLIT>
__device__ void gemm2(SmemT& S, const float* __restrict__ W, int tid){
    constexpr int COLS = 2;
    constexpr int CU   = OUT/COLS;
    constexpr int KI   = IN/KSPLIT;
    constexpr int RH   = PNT/2;
    constexpr int PF   = 8;
    static_assert(CU*KSPLIT == NTHREADS, "thread mapping");
    static_assert(KI >= PF, "prefetch depth");
    const int o  = (tid % CU)*COLS;
    const int kg = tid / CU;
    const float* Wp = W + kg*KI*OUT + o;
    const unsigned long long* Ap =
        reinterpret_cast<const unsigned long long*>(S.As) + kg*KI*(PS/2);

    float2 wbuf[PF];
    #pragma unroll
    for(int k=0;k<PF;k++) wbuf[k] = *reinterpret_cast<const float2*>(Wp + k*OUT);

    unsigned long long acc[COLS][RH];
    #pragma unroll
    for(int c=0;c<COLS;c++){
        #pragma unroll
        for(int r=0;r<RH;r++) acc[c][r]=0ull;
    }

    #pragma unroll 8
    for(int i=0;i<KI;i++){
        float2 w = wbuf[i&(PF-1)];
        if(i+PF<KI) wbuf[i&(PF-1)] = *reinterpret_cast<const float2*>(Wp + (i+PF)*OUT);
        unsigned long long w0 = pack2f(w.x,w.x);
        unsigned long long w1 = pack2f(w.y,w.y);
        const unsigned long long* a = Ap + i*(PS/2);
        #pragma unroll
        for(int r=0;r<RH;r++){
            unsigned long long av = a[r];       // warp-broadcast LDS.64
            acc[0][r] = ffma2(av, w0, acc[0][r]);
            acc[1][r] = ffma2(av, w1, acc[1][r]);
        }
    }
    #pragma unroll
    for(int c=0;c<COLS;c++){
        unsigned long long* dst =
            reinterpret_cast<unsigned long long*>(&S.Bw[(o+c+kg*OUT)*PS]);
        #pragma unroll
        for(int r=0;r<RH;r++) dst[r]=acc[c][r];
    }
}

// ---- As[o][t] = relu( sum_s NmT[s][t] * (sum_kg Bw[o+kg*OUT][s]) + bias[o] ) ----
// Packed f32x2 over contiguous t; NmT row is one set of broadcast LDS.64
// shared across all outputs this thread owns. NO SYNCS inside (early return).
template<int OUT,int KSPLIT>
__device__ void aggregate2(SmemT& S, const float* __restrict__ bias, int tid){
    constexpr int NO = (OUT >= NTHREADS) ? OUT/NTHREADS : 1;
    if(OUT < NTHREADS && tid >= OUT) return;
    constexpr int TH = PNT/2;
    unsigned long long acc[NO][TH];
    #pragma unroll
    for(int j=0;j<NO;j++){
        #pragma unroll
        for(int th=0;th<TH;th++) acc[j][th]=0ull;
    }
    #pragma unroll 4
    for(int s=0;s<PNT;s++){
        unsigned long long vv[NO];
        #pragma unroll
        for(int j=0;j<NO;j++){
            int row = tid + j*NTHREADS;
            float v = S.Bw[row*PS+s];
            #pragma unroll
            for(int kg=1;kg<KSPLIT;kg++) v += S.Bw[(row+kg*OUT)*PS+s];
            vv[j]=pack2f(v,v);
        }
        const unsigned long long* nm =
            reinterpret_cast<const unsigned long long*>(&S.NmT[s*PS]);
        #pragma unroll
        for(int th=0;th<TH;th++){
            unsigned long long nmv = nm[th];    // warp-broadcast LDS.64
            #pragma unroll
            for(int j=0;j<NO;j++) acc[j][th]=ffma2(nmv, vv[j], acc[j][th]);
        }
    }
    #pragma unroll
    for(int j=0;j<NO;j++){
        int o = tid + j*NTHREADS;
        float bo = bias[o];
        #pragma unroll
        for(int th=0;th<TH;th++){
            float lo = __uint_as_float((unsigned)(acc[j][th] & 0xffffffffull));
            float hi = __uint_as_float((unsigned)(acc[j][th] >> 32));
            float2 r;
            r.x = fmaxf(lo+bo, 0.f);
            r.y = fmaxf(hi+bo, 0.f);
            *reinterpret_cast<float2*>(&S.As[o*PS + 2*th]) = r;
        }
    }
}

__global__ void __launch_bounds__(NTHREADS,2)
gnn_kernel(const float* __restrict__ x,
           const float* __restrict__ W1, const float* __restrict__ b1,
           const float* __restrict__ W2, const float* __restrict__ b2,
           const float* __restrict__ W3, const float* __restrict__ b3,
           const float* __restrict__ W4, const float* __restrict__ b4,
           const float* __restrict__ W5, const float* __restrict__ b5,
           float* __restrict__ out)
{
    extern __shared__ char smem_raw[];
    SmemT& S = *reinterpret_cast<SmemT*>(smem_raw);
    const int tid = threadIdx.x;
    const long long b = blockIdx.x;

    // load sample b, transpose to feature-major
    const float* xb = x + b*(long long)(PNT*D0);
    for(int q=tid;q<PNT*D0;q+=NTHREADS){
        int p=q>>7, d=q&127;
        S.As[d*PS+p]=xb[q];
    }
    __syncthreads();

    // layer 1: 128 -> 256  (K-split 2: W1 read exactly once per CTA)
    build_graph<128>(S,tid);
    gemm2<128,256,2>(S,W1,tid);
    __syncthreads();
    aggregate2<256,2>(S,b1,tid);
    __syncthreads();
    // layer 2: 256 -> 512
    build_graph<256>(S,tid);
    gemm2<256,512,1>(S,W2,tid);
    __syncthreads();
    aggregate2<512,1>(S,b2,tid);
    __syncthreads();
    // layer 3: 512 -> 128  (K-split 4)
    build_graph<512>(S,tid);
    gemm2<512,128,4>(S,W3,tid);
    __syncthreads();
    aggregate2<128,4>(S,b3,tid);
    __syncthreads();

    // head: mean pool -> fc 128x64 relu -> fc 64x3 -> softmax
    if(tid<128){
        float s=0.f;
        #pragma unroll
        for(int p=0;p<PNT;p++) s+=S.As[tid*PS+p];
        S.msm[tid]=s*(1.f/PNT);
    }
    __syncthreads();
    if(tid<64){
        float a=b4[tid];
        #pragma unroll 4
        for(int f=0;f<128;f++) a=fmaf(S.msm[f], W4[f*64+tid], a);
        S.hsm[tid]=fmaxf(a,0.f);
    }
    __syncthreads();
    if(tid<3){
        float a=b5[tid];
        #pragma unroll
        for(int j=0;j<64;j++) a=fmaf(S.hsm[j], W5[j*3+tid], a);
        S.lsm[tid]=a;
    }
    __syncthreads();
    if(tid==0){
        float l0=S.lsm[0], l1=S.lsm[1], l2=S.lsm[2];
        float m=fmaxf(l0,fmaxf(l1,l2));
        float e0=expf(l0-m), e1=expf(l1-m), e2=expf(l2-m);
        float s=e0+e1+e2;
        out[b*3+0]=e0/s; out[b*3+1]=e1/s; out[b*3+2]=e2/s;
    }
}

extern "C" void kernel_launch(void* const* d_in, const int* in_sizes, int n_in,
                              void* d_out, int out_size){
    const float* x  = (const float*)d_in[0];
    const float* W1 = (const float*)d_in[1];
    const float* b1 = (const float*)d_in[2];
    const float* W2 = (const float*)d_in[3];
    const float* b2 = (const float*)d_in[4];
    const float* W3 = (const float*)d_in[5];
    const float* b3 = (const float*)d_in[6];
    const float* W4 = (const float*)d_in[7];
    const float* b4 = (const float*)d_in[8];
    const float* W5 = (const float*)d_in[9];
    const float* b5 = (const float*)d_in[10];
    float* out = (float*)d_out;

    int N = in_sizes[0]/(PNT*D0);
    size_t smem = sizeof(SmemT);
    cudaFuncSetAttribute(gnn_kernel, cudaFuncAttributeMaxDynamicSharedMemorySize, (int)smem);
    gnn_kernel<<<N, NTHREADS, smem>>>(x, W1,b1, W2,b2, W3,b3, W4,b4, W5,b5, out);
}